// round 12
// baseline (speedup 1.0000x reference)
#include <cuda_runtime.h>
#include <cuda_bf16.h>
#include <math.h>
#include <stdint.h>

#define CDIM   192
#define KVDIM  384
#define HEADS  6
#define CPH    32
#define WIDTH  160
#define HW     25600          // 160*160
#define BATCH  8
#define NSPLIT 16

// ---------------- scratch (device globals; no allocation) ----------------
__device__ float g_q   [(size_t)BATCH * CDIM  * HW];   // q after 1x1
__device__ float g_kv  [(size_t)BATCH * KVDIM * HW];   // kv after 1x1
__device__ float g_qd  [(size_t)BATCH * CDIM  * HW];   // q after dw3x3
__device__ float g_kvd [(size_t)BATCH * KVDIM * HW];   // k|v after dw3x3
__device__ float g_S   [BATCH * HEADS * CPH * CPH];    // raw gram
__device__ float g_NQ  [BATCH * HEADS * CPH];          // sum q^2
__device__ float g_NK  [BATCH * HEADS * CPH];          // sum k^2
__device__ float g_A   [BATCH * HEADS * CPH * CPH];    // softmax(attn)
// pre-split bf16 weights (hi/lo) for tensor-core GEMMs
__device__ __nv_bfloat16 g_Wqh [CDIM  * CDIM];
__device__ __nv_bfloat16 g_Wql [CDIM  * CDIM];
__device__ __nv_bfloat16 g_Wkvh[KVDIM * CDIM];
__device__ __nv_bfloat16 g_Wkvl[KVDIM * CDIM];
__device__ __nv_bfloat16 g_Mh  [BATCH * CDIM * CDIM];  // W_out @ blockdiag(A), hi
__device__ __nv_bfloat16 g_Ml  [BATCH * CDIM * CDIM];  // lo

// ================= warp-MMA helpers (arch-agnostic PTX) =================
__device__ __forceinline__ uint32_t smem_u32(const void* p) {
    uint32_t a;
    asm("{ .reg .u64 t; cvta.to.shared.u64 t, %1; cvt.u32.u64 %0, t; }" : "=r"(a) : "l"(p));
    return a;
}
__device__ __forceinline__ void ldsm_x4(uint32_t (&r)[4], uint32_t addr) {
    asm volatile("ldmatrix.sync.aligned.m8n8.x4.shared.b16 {%0,%1,%2,%3}, [%4];"
        : "=r"(r[0]), "=r"(r[1]), "=r"(r[2]), "=r"(r[3]) : "r"(addr));
}
__device__ __forceinline__ void ldsm_x4_t(uint32_t (&r)[4], uint32_t addr) {
    asm volatile("ldmatrix.sync.aligned.m8n8.x4.trans.shared.b16 {%0,%1,%2,%3}, [%4];"
        : "=r"(r[0]), "=r"(r[1]), "=r"(r[2]), "=r"(r[3]) : "r"(addr));
}
__device__ __forceinline__ void mma_bf16(float (&d)[4], const uint32_t (&a)[4],
                                         uint32_t b0, uint32_t b1) {
    asm volatile("mma.sync.aligned.m16n8k16.row.col.f32.bf16.bf16.f32 "
        "{%0,%1,%2,%3}, {%4,%5,%6,%7}, {%8,%9}, {%0,%1,%2,%3};"
        : "+f"(d[0]), "+f"(d[1]), "+f"(d[2]), "+f"(d[3])
        : "r"(a[0]), "r"(a[1]), "r"(a[2]), "r"(a[3]), "r"(b0), "r"(b1));
}

// ============ tensor-core GEMM (mma.sync bf16, 3-term fp32 split) ============
// Y[(b*Ostride + o)*HW + n] = sum_k W[o][k] * X[b][k][n],  o in [0,192)
// Block: 192 couts (3 o-tiles of 64) x BN=128 spatial, BK=32. X staged ONCE.
// 256 thr = 2x4 warps; warp = 32m x 32n within each o-tile.
#define APAD 40     // A row = 80 B: ldmatrix conflict-free, 16B-aligned
#define BPAD 136    // B row = 272 B: conflict-free

__global__ __launch_bounds__(256) void gemm_mma2(
    const __nv_bfloat16* __restrict__ Wh, const __nv_bfloat16* __restrict__ Wl,
    const float* __restrict__ X, float* __restrict__ Y,
    int Ostride, long wBatch, long xBatch)
{
    __shared__ __align__(16) __nv_bfloat16 sA[2][192][APAD];  // [hi/lo][m][k]
    __shared__ __align__(16) __nv_bfloat16 sB[2][32][BPAD];   // [hi/lo][k][n]

    const int tid  = threadIdx.x;
    const int wid  = tid >> 5, lane = tid & 31;
    const int wm   = wid >> 2;          // 0..1  -> m offset *32 within o-tile
    const int wn   = wid & 3;           // 0..3  -> n offset *32
    const int n0   = blockIdx.x * 128;
    const int b    = blockIdx.z;

    const __nv_bfloat16* Whb = Wh + (size_t)b * wBatch;
    const __nv_bfloat16* Wlb = Wl + (size_t)b * wBatch;
    const float* Xb = X + (size_t)b * xBatch + n0;

    const int aRow = (lane & 7) + ((lane >> 3) & 1) * 8;
    const int aCol = ((lane >> 4) & 1) * 8;
    const int bRow = (lane & 7) + ((lane >> 3) & 1) * 8;
    const int bCol = ((lane >> 4) & 1) * 8;

    const uint32_t sA0 = smem_u32(&sA[0][0][0]);
    const uint32_t sA1 = smem_u32(&sA[1][0][0]);
    const uint32_t sB0 = smem_u32(&sB[0][0][0]);
    const uint32_t sB1 = smem_u32(&sB[1][0][0]);

    float acc[3][2][4][4] = {};   // [ot][mt][nt][frag]

    for (int kb = 0; kb < 6; kb++) {
        const int k0 = kb * 32;
        // ---- stage A: W chunk [192 m x 32 k], hi and lo (pure copy) ----
        #pragma unroll
        for (int i = 0; i < 6; i++) {
            int f = tid + i * 256;             // 0..1535 groups of 4 bf16
            int m = f >> 3, k4 = (f & 7) * 4;
            uint2 vh = *(const uint2*)(Whb + (size_t)m * CDIM + k0 + k4);
            uint2 vl = *(const uint2*)(Wlb + (size_t)m * CDIM + k0 + k4);
            *(uint2*)&sA[0][m][k4] = vh;
            *(uint2*)&sA[1][m][k4] = vl;
        }
        // ---- stage B: X chunk [32 k x 128 n] fp32 -> bf16 hi/lo (once) ----
        #pragma unroll
        for (int i = 0; i < 4; i++) {
            int f = tid + i * 256;             // 0..1023 float4 groups
            int k = f >> 5, n4 = (f & 31) * 4;
            float4 v = *(const float4*)(Xb + (size_t)(k0 + k) * HW + n4);
            __nv_bfloat16 h0 = __float2bfloat16(v.x), h1 = __float2bfloat16(v.y);
            __nv_bfloat16 h2 = __float2bfloat16(v.z), h3 = __float2bfloat16(v.w);
            __nv_bfloat16 l0 = __float2bfloat16(v.x - __bfloat162float(h0));
            __nv_bfloat16 l1 = __float2bfloat16(v.y - __bfloat162float(h1));
            __nv_bfloat16 l2 = __float2bfloat16(v.z - __bfloat162float(h2));
            __nv_bfloat16 l3 = __float2bfloat16(v.w - __bfloat162float(h3));
            uint2 ph, pl;
            ph.x = (uint32_t)__bfloat16_as_ushort(h0) | ((uint32_t)__bfloat16_as_ushort(h1) << 16);
            ph.y = (uint32_t)__bfloat16_as_ushort(h2) | ((uint32_t)__bfloat16_as_ushort(h3) << 16);
            pl.x = (uint32_t)__bfloat16_as_ushort(l0) | ((uint32_t)__bfloat16_as_ushort(l1) << 16);
            pl.y = (uint32_t)__bfloat16_as_ushort(l2) | ((uint32_t)__bfloat16_as_ushort(l3) << 16);
            *(uint2*)&sB[0][k][n4] = ph;
            *(uint2*)&sB[1][k][n4] = pl;
        }
        __syncthreads();

        #pragma unroll
        for (int ks = 0; ks < 2; ks++) {
            uint32_t bh[2][4], bl[2][4];
            #pragma unroll
            for (int np = 0; np < 2; np++) {
                uint32_t off = (uint32_t)((ks * 16 + bRow) * BPAD
                                          + wn * 32 + np * 16 + bCol) * 2;
                ldsm_x4_t(bh[np], sB0 + off);
                ldsm_x4_t(bl[np], sB1 + off);
            }
            #pragma unroll
            for (int ot = 0; ot < 3; ot++) {
                uint32_t ah[2][4], al[2][4];
                #pragma unroll
                for (int mt = 0; mt < 2; mt++) {
                    uint32_t off = (uint32_t)((ot * 64 + wm * 32 + mt * 16 + aRow) * APAD
                                              + ks * 16 + aCol) * 2;
                    ldsm_x4(ah[mt], sA0 + off);
                    ldsm_x4(al[mt], sA1 + off);
                }
                #pragma unroll
                for (int mt = 0; mt < 2; mt++)
                    #pragma unroll
                    for (int np = 0; np < 2; np++)
                        #pragma unroll
                        for (int s = 0; s < 2; s++) {
                            int nt = np * 2 + s;
                            mma_bf16(acc[ot][mt][nt], ah[mt], bh[np][s*2], bh[np][s*2+1]);
                            mma_bf16(acc[ot][mt][nt], ah[mt], bl[np][s*2], bl[np][s*2+1]);
                            mma_bf16(acc[ot][mt][nt], al[mt], bh[np][s*2], bh[np][s*2+1]);
                        }
            }
        }
        __syncthreads();
    }

    // ---- epilogue: D m16n8 fragments -> float2 stores ----
    const int g = lane >> 2, cc = (lane & 3) * 2;
    #pragma unroll
    for (int ot = 0; ot < 3; ot++) {
        #pragma unroll
        for (int mt = 0; mt < 2; mt++) {
            #pragma unroll
            for (int nt = 0; nt < 4; nt++) {
                int orow = ot * 64 + wm * 32 + mt * 16 + g;
                int ncol = n0 + wn * 32 + nt * 8 + cc;
                float2 v0 = make_float2(acc[ot][mt][nt][0], acc[ot][mt][nt][1]);
                float2 v1 = make_float2(acc[ot][mt][nt][2], acc[ot][mt][nt][3]);
                *(float2*)&Y[((size_t)b * Ostride + orow    ) * HW + ncol] = v0;
                *(float2*)&Y[((size_t)b * Ostride + orow + 8) * HW + ncol] = v1;
            }
        }
    }
}

// ---------------- split fp32 weights into bf16 hi/lo ----------------------
__global__ void split_w(const float* __restrict__ wq, const float* __restrict__ wkv) {
    int i = blockIdx.x * 256 + threadIdx.x;
    if (i < CDIM * CDIM) {
        float f = wq[i];
        __nv_bfloat16 h = __float2bfloat16(f);
        g_Wqh[i] = h;
        g_Wql[i] = __float2bfloat16(f - __bfloat162float(h));
    }
    if (i < KVDIM * CDIM) {
        float f = wkv[i];
        __nv_bfloat16 h = __float2bfloat16(f);
        g_Wkvh[i] = h;
        g_Wkvl[i] = __float2bfloat16(f - __bfloat162float(h));
    }
}

// ---------------- depthwise 3x3, pad 1 — row-strip smem version -----------
__global__ __launch_bounds__(160) void dwconv3x3_v2(
    const float* __restrict__ X, const float* __restrict__ Wd,
    float* __restrict__ Y, int C)
{
    __shared__ float s[10][WIDTH];
    const int b = blockIdx.z, ch = blockIdx.y;
    const int r0 = blockIdx.x * 8;
    const int w = threadIdx.x;                 // 0..159, fixed column
    const float* xp = X + ((size_t)b * C + ch) * HW;
    #pragma unroll
    for (int i = 0; i < 10; i++) {
        int r = r0 - 1 + i;
        s[i][w] = (r >= 0 && r < WIDTH) ? xp[r * WIDTH + w] : 0.f;
    }
    const float* wp = Wd + ch * 9;
    float c00 = wp[0], c01 = wp[1], c02 = wp[2];
    float c10 = wp[3], c11 = wp[4], c12 = wp[5];
    float c20 = wp[6], c21 = wp[7], c22 = wp[8];
    __syncthreads();
    const bool wl = (w > 0), wr = (w < WIDTH - 1);
    float* yp = Y + ((size_t)b * C + ch) * HW + r0 * WIDTH + w;
    #pragma unroll
    for (int r = 0; r < 8; r++) {
        float a0 = wl ? s[r][w-1] : 0.f, a1 = s[r][w],   a2 = wr ? s[r][w+1] : 0.f;
        float b0 = wl ? s[r+1][w-1] : 0.f, b1 = s[r+1][w], b2 = wr ? s[r+1][w+1] : 0.f;
        float d0 = wl ? s[r+2][w-1] : 0.f, d1 = s[r+2][w], d2 = wr ? s[r+2][w+1] : 0.f;
        float acc = c00*a0 + c01*a1 + c02*a2
                  + c10*b0 + c11*b1 + c12*b2
                  + c20*d0 + c21*d1 + c22*d2;
        yp[r * WIDTH] = acc;
    }
}

// ---------------- zero the gram accumulators -------------------------------
__global__ void zero_acc() {
    int i = blockIdx.x * 256 + threadIdx.x;
    const int nS = BATCH * HEADS * CPH * CPH;
    const int nN = BATCH * HEADS * CPH;
    if (i < nS) g_S[i] = 0.f;
    if (i < nN) { g_NQ[i] = 0.f; g_NK[i] = 0.f; }
}

// ---------------- Gram: S[b,h,c,d] = sum_n q[c,n] k[d,n]; plus sum q^2, k^2
__global__ __launch_bounds__(256) void gram(
    const float* __restrict__ Q, const float* __restrict__ K)
{
    __shared__ float qs[32][33];
    __shared__ float ks[32][33];
    const int b = blockIdx.z, hh = blockIdx.y, split = blockIdx.x;
    const int tid = threadIdx.x;
    const float* qb = Q + ((size_t)b * CDIM  + hh * CPH) * HW;
    const float* kb = K + ((size_t)b * KVDIM + hh * CPH) * HW;
    const int chunk = HW / NSPLIT;
    const int nbeg = split * chunk;
    const int ty = tid >> 4, tx = tid & 15;
    const int lc = tid >> 3;
    const int lj = (tid & 7) * 4;

    float acc00 = 0, acc01 = 0, acc10 = 0, acc11 = 0;
    float aq0 = 0, aq1 = 0, ak0 = 0, ak1 = 0;

    for (int n0 = nbeg; n0 < nbeg + chunk; n0 += 32) {
        float4 vq = *(const float4*)&qb[(size_t)lc * HW + n0 + lj];
        float4 vk = *(const float4*)&kb[(size_t)lc * HW + n0 + lj];
        qs[lc][lj] = vq.x; qs[lc][lj+1] = vq.y; qs[lc][lj+2] = vq.z; qs[lc][lj+3] = vq.w;
        ks[lc][lj] = vk.x; ks[lc][lj+1] = vk.y; ks[lc][lj+2] = vk.z; ks[lc][lj+3] = vk.w;
        __syncthreads();
        #pragma unroll
        for (int t = 0; t < 32; t++) {
            float q0 = qs[ty*2][t],  q1 = qs[ty*2+1][t];
            float k0 = ks[tx*2][t],  k1 = ks[tx*2+1][t];
            acc00 += q0*k0; acc01 += q0*k1; acc10 += q1*k0; acc11 += q1*k1;
            if (tx == 0) { aq0 += q0*q0; aq1 += q1*q1; }
            if (ty == 0) { ak0 += k0*k0; ak1 += k1*k1; }
        }
        __syncthreads();
    }
    float* Sb = g_S + (size_t)(b * HEADS + hh) * CPH * CPH;
    atomicAdd(&Sb[(ty*2    ) * CPH + tx*2    ], acc00);
    atomicAdd(&Sb[(ty*2    ) * CPH + tx*2 + 1], acc01);
    atomicAdd(&Sb[(ty*2 + 1) * CPH + tx*2    ], acc10);
    atomicAdd(&Sb[(ty*2 + 1) * CPH + tx*2 + 1], acc11);
    if (tx == 0) {
        atomicAdd(&g_NQ[(b * HEADS + hh) * CPH + ty*2    ], aq0);
        atomicAdd(&g_NQ[(b * HEADS + hh) * CPH + ty*2 + 1], aq1);
    }
    if (ty == 0) {
        atomicAdd(&g_NK[(b * HEADS + hh) * CPH + tx*2    ], ak0);
        atomicAdd(&g_NK[(b * HEADS + hh) * CPH + tx*2 + 1], ak1);
    }
}

// ---------------- softmax over d with L2-norm scaling + temperature --------
__global__ void softmax_attn(const float* __restrict__ temp) {
    const int bh = blockIdx.x;
    const int h  = bh % HEADS;
    const int d  = threadIdx.x;
    const float t = temp[h];
    float nk = fmaxf(sqrtf(g_NK[bh * CPH + d]), 1e-12f);
    for (int c = 0; c < CPH; c++) {
        float nq = fmaxf(sqrtf(g_NQ[bh * CPH + c]), 1e-12f);
        float v = g_S[bh * CPH * CPH + c * CPH + d] / (nq * nk) * t;
        float m = v;
        #pragma unroll
        for (int o = 16; o; o >>= 1) m = fmaxf(m, __shfl_xor_sync(~0u, m, o));
        float e = __expf(v - m);
        float s = e;
        #pragma unroll
        for (int o = 16; o; o >>= 1) s += __shfl_xor_sync(~0u, s, o);
        g_A[bh * CPH * CPH + c * CPH + d] = e / s;
    }
}

// ---------------- fold: M[b,o,g] = sum_c Wout[o, h*32+c] * A[b,h,c,d] ------
// emits bf16 hi/lo directly for the tensor-core final GEMM
__global__ __launch_bounds__(256) void foldM(const float* __restrict__ Wout) {
    const int b = blockIdx.y;
    const int idx = blockIdx.x * 256 + threadIdx.x;     // 0..192*192-1
    const int o = idx / CDIM, g = idx % CDIM;
    const int h = g / CPH, d = g % CPH;
    const float* Ab = g_A + (size_t)(b * HEADS + h) * CPH * CPH;
    float acc = 0.f;
    #pragma unroll
    for (int c = 0; c < CPH; c++)
        acc += Wout[o * CDIM + h * CPH + c] * Ab[c * CPH + d];
    __nv_bfloat16 hh = __float2bfloat16(acc);
    g_Mh[(size_t)b * CDIM * CDIM + idx] = hh;
    g_Ml[(size_t)b * CDIM * CDIM + idx] = __float2bfloat16(acc - __bfloat162float(hh));
}

// ---------------- launch --------------------------------------------------
extern "C" void kernel_launch(void* const* d_in, const int* in_sizes, int n_in,
                              void* d_out, int out_size)
{
    const float* x_q   = (const float*)d_in[0];
    const float* x_kv  = (const float*)d_in[1];
    const float* w_q   = (const float*)d_in[2];
    const float* w_kv  = (const float*)d_in[3];
    const float* w_qdw = (const float*)d_in[4];
    const float* w_kvdw= (const float*)d_in[5];
    const float* w_out = (const float*)d_in[6];
    const float* temp  = (const float*)d_in[7];
    float* out = (float*)d_out;

    float *bq, *bkv, *bqd, *bkvd;
    __nv_bfloat16 *wqh, *wql, *wkvh, *wkvl, *mh, *ml;
    cudaGetSymbolAddress((void**)&bq,   g_q);
    cudaGetSymbolAddress((void**)&bkv,  g_kv);
    cudaGetSymbolAddress((void**)&bqd,  g_qd);
    cudaGetSymbolAddress((void**)&bkvd, g_kvd);
    cudaGetSymbolAddress((void**)&wqh,  g_Wqh);
    cudaGetSymbolAddress((void**)&wql,  g_Wql);
    cudaGetSymbolAddress((void**)&wkvh, g_Wkvh);
    cudaGetSymbolAddress((void**)&wkvl, g_Wkvl);
    cudaGetSymbolAddress((void**)&mh,   g_Mh);
    cudaGetSymbolAddress((void**)&ml,   g_Ml);

    // 0) split weights to bf16 hi/lo
    split_w<<<(KVDIM * CDIM + 255) / 256, 256>>>(w_q, w_kv);
    // 1) q = W_q @ x_q   (192 couts per block; X staged once)
    gemm_mma2<<<dim3(HW/128, 1, BATCH), 256>>>(
        wqh, wql, x_q, bq, CDIM, 0, (long)CDIM * HW);
    // 2a) k = W_kv[0:192] @ x_kv
    gemm_mma2<<<dim3(HW/128, 1, BATCH), 256>>>(
        wkvh, wkvl, x_kv, bkv, KVDIM, 0, (long)CDIM * HW);
    // 2b) v = W_kv[192:384] @ x_kv
    gemm_mma2<<<dim3(HW/128, 1, BATCH), 256>>>(
        wkvh + (size_t)CDIM * CDIM, wkvl + (size_t)CDIM * CDIM, x_kv,
        bkv + (size_t)CDIM * HW, KVDIM, 0, (long)CDIM * HW);
    // 3) depthwise 3x3
    dwconv3x3_v2<<<dim3(WIDTH/8, CDIM,  BATCH), WIDTH>>>(bq,  w_qdw,  bqd,  CDIM);
    dwconv3x3_v2<<<dim3(WIDTH/8, KVDIM, BATCH), WIDTH>>>(bkv, w_kvdw, bkvd, KVDIM);
    // 4) zero gram accumulators
    zero_acc<<<(BATCH*HEADS*CPH*CPH + 255)/256, 256>>>();
    // 5) gram + norms (k = first DIM channels of kvd)
    gram<<<dim3(NSPLIT, HEADS, BATCH), 256>>>(bqd, bkvd);
    // 6) softmax with normalization + temperature
    softmax_attn<<<BATCH * HEADS, 32>>>(temp);
    // 7) fold W_out with attention -> bf16 hi/lo M
    foldM<<<dim3(CDIM*CDIM/256, BATCH), 256>>>(w_out);
    // 8) out = M_b @ v   (v = second DIM channels of kvd)
    gemm_mma2<<<dim3(HW/128, 1, BATCH), 256>>>(
        mh, ml, bkvd + (size_t)CDIM * HW, out, CDIM,
        (long)CDIM * CDIM, (long)KVDIM * HW);
}

// round 14
// speedup vs baseline: 1.0931x; 1.0931x over previous
#include <cuda_runtime.h>
#include <cuda_bf16.h>
#include <math.h>
#include <stdint.h>

#define CDIM   192
#define KVDIM  384
#define HEADS  6
#define CPH    32
#define WIDTH  160
#define HW     25600          // 160*160
#define BATCH  8
#define NSPLIT 16

// ---------------- scratch (device globals; no allocation) ----------------
__device__ float g_q   [(size_t)BATCH * CDIM  * HW];   // q after 1x1
__device__ float g_kv  [(size_t)BATCH * KVDIM * HW];   // kv after 1x1
__device__ float g_qd  [(size_t)BATCH * CDIM  * HW];   // q after dw3x3
__device__ float g_kvd [(size_t)BATCH * KVDIM * HW];   // k after dw3x3 (first half used)
__device__ float g_S   [BATCH * HEADS * CPH * CPH];    // raw gram
__device__ float g_NQ  [BATCH * HEADS * CPH];          // sum q^2
__device__ float g_NK  [BATCH * HEADS * CPH];          // sum k^2
__device__ float g_A   [BATCH * HEADS * CPH * CPH];    // softmax(attn)
// pre-split bf16 operands
__device__ __nv_bfloat16 g_Wqh [CDIM  * CDIM];
__device__ __nv_bfloat16 g_Wql [CDIM  * CDIM];
__device__ __nv_bfloat16 g_Wkvh[KVDIM * CDIM];
__device__ __nv_bfloat16 g_Wkvl[KVDIM * CDIM];
__device__ __nv_bfloat16 g_Mh  [BATCH * CDIM * CDIM];  // W_out @ blockdiag(A), hi
__device__ __nv_bfloat16 g_Ml  [BATCH * CDIM * CDIM];  // lo
__device__ __nv_bfloat16 g_Xqh [(size_t)BATCH * CDIM * HW];   // x_query hi
__device__ __nv_bfloat16 g_Xql [(size_t)BATCH * CDIM * HW];   // lo
__device__ __nv_bfloat16 g_Xkvh[(size_t)BATCH * CDIM * HW];   // x_key_value hi (192 ch!)
__device__ __nv_bfloat16 g_Xkvl[(size_t)BATCH * CDIM * HW];   // lo
__device__ __nv_bfloat16 g_Vh  [(size_t)BATCH * CDIM * HW];   // v after dw3x3, hi
__device__ __nv_bfloat16 g_Vl  [(size_t)BATCH * CDIM * HW];   // lo

// ================= warp-MMA + cp.async helpers (arch-agnostic PTX) ========
__device__ __forceinline__ uint32_t smem_u32(const void* p) {
    uint32_t a;
    asm("{ .reg .u64 t; cvta.to.shared.u64 t, %1; cvt.u32.u64 %0, t; }" : "=r"(a) : "l"(p));
    return a;
}
__device__ __forceinline__ void ldsm_x4(uint32_t (&r)[4], uint32_t addr) {
    asm volatile("ldmatrix.sync.aligned.m8n8.x4.shared.b16 {%0,%1,%2,%3}, [%4];"
        : "=r"(r[0]), "=r"(r[1]), "=r"(r[2]), "=r"(r[3]) : "r"(addr));
}
__device__ __forceinline__ void ldsm_x4_t(uint32_t (&r)[4], uint32_t addr) {
    asm volatile("ldmatrix.sync.aligned.m8n8.x4.trans.shared.b16 {%0,%1,%2,%3}, [%4];"
        : "=r"(r[0]), "=r"(r[1]), "=r"(r[2]), "=r"(r[3]) : "r"(addr));
}
__device__ __forceinline__ void mma_bf16(float (&d)[4], const uint32_t (&a)[4],
                                         uint32_t b0, uint32_t b1) {
    asm volatile("mma.sync.aligned.m16n8k16.row.col.f32.bf16.bf16.f32 "
        "{%0,%1,%2,%3}, {%4,%5,%6,%7}, {%8,%9}, {%0,%1,%2,%3};"
        : "+f"(d[0]), "+f"(d[1]), "+f"(d[2]), "+f"(d[3])
        : "r"(a[0]), "r"(a[1]), "r"(a[2]), "r"(a[3]), "r"(b0), "r"(b1));
}
#define CP16(dst, src) \
    asm volatile("cp.async.cg.shared.global [%0], [%1], 16;" :: "r"(dst), "l"(src))
#define CP_COMMIT() asm volatile("cp.async.commit_group;" ::: "memory")
#define CP_WAIT1()  asm volatile("cp.async.wait_group 1;" ::: "memory")
#define CP_WAIT0()  asm volatile("cp.async.wait_group 0;" ::: "memory")

// ============ bf16 tensor-core GEMM, double-buffered cp.async staging ======
// Y[(b*O + o0+m)*HW + n0+n] = sum_k A[o0+m][k] * B[b][k][n0+n]  (3-term split)
// BM=64, BN=128, BK=32; 256 thr = 2x4 warps; warp = 32m x 32n. K = 192 always.
#define APAD 40     // A row = 80 B (16B-aligned, ldmatrix conflict-free)
#define BPAD 136    // B row = 272 B
#define A_SZ 5120   // 64*40*2
#define B_SZ 8704   // 32*136*2
#define SM_TOTAL (4*A_SZ + 4*B_SZ)   // 55296 B
__device__ __forceinline__ uint32_t aOff(int buf, int hl) { return (uint32_t)(buf*2+hl)*A_SZ; }
__device__ __forceinline__ uint32_t bOff(int buf, int hl) { return 4*A_SZ + (uint32_t)(buf*2+hl)*B_SZ; }

__global__ __launch_bounds__(256, 2) void gemm_bf16(
    const __nv_bfloat16* __restrict__ Ah, const __nv_bfloat16* __restrict__ Al,
    const __nv_bfloat16* __restrict__ Bh, const __nv_bfloat16* __restrict__ Bl,
    float* __restrict__ Y, int O, long wBatch, long xBatch)
{
    extern __shared__ char smem[];
    const uint32_t sb = smem_u32(smem);

    const int tid  = threadIdx.x;
    const int wid  = tid >> 5, lane = tid & 31;
    const int wm   = wid >> 2;          // 0..1
    const int wn   = wid & 3;           // 0..3
    const int n0   = blockIdx.x * 128;
    const int o0   = blockIdx.y * 64;
    const int b    = blockIdx.z;

    const __nv_bfloat16* Ahb = Ah + (size_t)b * wBatch + (size_t)o0 * CDIM;
    const __nv_bfloat16* Alb = Al + (size_t)b * wBatch + (size_t)o0 * CDIM;
    const __nv_bfloat16* Bhb = Bh + (size_t)b * xBatch + n0;
    const __nv_bfloat16* Blb = Bl + (size_t)b * xBatch + n0;

    // staging coords (16B chunks)
    const int am = tid >> 2, ak = (tid & 3) * 8;          // A: 256 chunks
    const int bk0c = tid >> 4, bn0c = (tid & 15) * 8;     // B chunk 0
    const int bk1c = (tid + 256) >> 4, bn1c = ((tid + 256) & 15) * 8;

    // ldmatrix coords
    const int aRow = (lane & 7) + ((lane >> 3) & 1) * 8;
    const int aCol = ((lane >> 4) & 1) * 8;
    const int bRow = aRow, bCol = aCol;

    float acc[2][4][4] = {};

    // ---- stage k-block 0 into buf 0 ----
    {
        const int k0 = 0;
        CP16(sb + aOff(0,0) + (am*APAD + ak)*2, Ahb + (size_t)am * CDIM + k0 + ak);
        CP16(sb + aOff(0,1) + (am*APAD + ak)*2, Alb + (size_t)am * CDIM + k0 + ak);
        CP16(sb + bOff(0,0) + (bk0c*BPAD + bn0c)*2, Bhb + (size_t)(k0 + bk0c) * HW + bn0c);
        CP16(sb + bOff(0,1) + (bk0c*BPAD + bn0c)*2, Blb + (size_t)(k0 + bk0c) * HW + bn0c);
        CP16(sb + bOff(0,0) + (bk1c*BPAD + bn1c)*2, Bhb + (size_t)(k0 + bk1c) * HW + bn1c);
        CP16(sb + bOff(0,1) + (bk1c*BPAD + bn1c)*2, Blb + (size_t)(k0 + bk1c) * HW + bn1c);
        CP_COMMIT();
    }

    int buf = 0;
    #pragma unroll 1
    for (int kb = 0; kb < 6; kb++) {
        if (kb < 5) {                       // stage next block into other buffer
            const int k0 = (kb + 1) * 32;
            const int nb = buf ^ 1;
            CP16(sb + aOff(nb,0) + (am*APAD + ak)*2, Ahb + (size_t)am * CDIM + k0 + ak);
            CP16(sb + aOff(nb,1) + (am*APAD + ak)*2, Alb + (size_t)am * CDIM + k0 + ak);
            CP16(sb + bOff(nb,0) + (bk0c*BPAD + bn0c)*2, Bhb + (size_t)(k0 + bk0c) * HW + bn0c);
            CP16(sb + bOff(nb,1) + (bk0c*BPAD + bn0c)*2, Blb + (size_t)(k0 + bk0c) * HW + bn0c);
            CP16(sb + bOff(nb,0) + (bk1c*BPAD + bn1c)*2, Bhb + (size_t)(k0 + bk1c) * HW + bn1c);
            CP16(sb + bOff(nb,1) + (bk1c*BPAD + bn1c)*2, Blb + (size_t)(k0 + bk1c) * HW + bn1c);
            CP_COMMIT();
            CP_WAIT1();                      // current block's group done
        } else {
            CP_WAIT0();
        }
        __syncthreads();

        #pragma unroll
        for (int ks = 0; ks < 2; ks++) {
            uint32_t ah[2][4], al[2][4], bh[2][4], bl[2][4];
            #pragma unroll
            for (int mt = 0; mt < 2; mt++) {
                uint32_t off = (uint32_t)((wm * 32 + mt * 16 + aRow) * APAD + ks * 16 + aCol) * 2;
                ldsm_x4(ah[mt], sb + aOff(buf,0) + off);
                ldsm_x4(al[mt], sb + aOff(buf,1) + off);
            }
            #pragma unroll
            for (int np = 0; np < 2; np++) {
                uint32_t off = (uint32_t)((ks * 16 + bRow) * BPAD + wn * 32 + np * 16 + bCol) * 2;
                ldsm_x4_t(bh[np], sb + bOff(buf,0) + off);
                ldsm_x4_t(bl[np], sb + bOff(buf,1) + off);
            }
            #pragma unroll
            for (int mt = 0; mt < 2; mt++)
                #pragma unroll
                for (int np = 0; np < 2; np++)
                    #pragma unroll
                    for (int s = 0; s < 2; s++) {
                        int nt = np * 2 + s;
                        mma_bf16(acc[mt][nt], ah[mt], bh[np][s*2], bh[np][s*2+1]); // hi*hi
                        mma_bf16(acc[mt][nt], ah[mt], bl[np][s*2], bl[np][s*2+1]); // hi*lo
                        mma_bf16(acc[mt][nt], al[mt], bh[np][s*2], bh[np][s*2+1]); // lo*hi
                    }
        }
        __syncthreads();                     // compute done before buf is overwritten
        buf ^= 1;
    }

    // ---- epilogue ----
    const int g = lane >> 2, cc = (lane & 3) * 2;
    #pragma unroll
    for (int mt = 0; mt < 2; mt++) {
        #pragma unroll
        for (int nt = 0; nt < 4; nt++) {
            int orow = o0 + wm * 32 + mt * 16 + g;
            int ncol = n0 + wn * 32 + nt * 8 + cc;
            float2 v0 = make_float2(acc[mt][nt][0], acc[mt][nt][1]);
            float2 v1 = make_float2(acc[mt][nt][2], acc[mt][nt][3]);
            *(float2*)&Y[((size_t)b * O + orow    ) * HW + ncol] = v0;
            *(float2*)&Y[((size_t)b * O + orow + 8) * HW + ncol] = v1;
        }
    }
}

// ---------------- split fp32 weights into bf16 hi/lo ----------------------
__global__ void split_w(const float* __restrict__ wq, const float* __restrict__ wkv) {
    int i = blockIdx.x * 256 + threadIdx.x;
    if (i < CDIM * CDIM) {
        float f = wq[i];
        __nv_bfloat16 h = __float2bfloat16(f);
        g_Wqh[i] = h;
        g_Wql[i] = __float2bfloat16(f - __bfloat162float(h));
    }
    if (i < KVDIM * CDIM) {
        float f = wkv[i];
        __nv_bfloat16 h = __float2bfloat16(f);
        g_Wkvh[i] = h;
        g_Wkvl[i] = __float2bfloat16(f - __bfloat162float(h));
    }
}

// ---------------- split fp32 activations into bf16 hi/lo ------------------
// x_query AND x_key_value are both [BATCH, CDIM=192, HW].
__device__ __forceinline__ void split4(float4 v, uint2& ph, uint2& pl) {
    __nv_bfloat16 h0 = __float2bfloat16(v.x), h1 = __float2bfloat16(v.y);
    __nv_bfloat16 h2 = __float2bfloat16(v.z), h3 = __float2bfloat16(v.w);
    __nv_bfloat16 l0 = __float2bfloat16(v.x - __bfloat162float(h0));
    __nv_bfloat16 l1 = __float2bfloat16(v.y - __bfloat162float(h1));
    __nv_bfloat16 l2 = __float2bfloat16(v.z - __bfloat162float(h2));
    __nv_bfloat16 l3 = __float2bfloat16(v.w - __bfloat162float(h3));
    ph.x = (uint32_t)__bfloat16_as_ushort(h0) | ((uint32_t)__bfloat16_as_ushort(h1) << 16);
    ph.y = (uint32_t)__bfloat16_as_ushort(h2) | ((uint32_t)__bfloat16_as_ushort(h3) << 16);
    pl.x = (uint32_t)__bfloat16_as_ushort(l0) | ((uint32_t)__bfloat16_as_ushort(l1) << 16);
    pl.y = (uint32_t)__bfloat16_as_ushort(l2) | ((uint32_t)__bfloat16_as_ushort(l3) << 16);
}
__global__ __launch_bounds__(256) void split_x(
    const float* __restrict__ xq, const float* __restrict__ xkv)
{
    const size_t i = (size_t)blockIdx.x * 256 + threadIdx.x;      // float4 index
    uint2 ph, pl;
    split4(((const float4*)xq)[i], ph, pl);
    ((uint2*)g_Xqh)[i] = ph;
    ((uint2*)g_Xql)[i] = pl;
    split4(((const float4*)xkv)[i], ph, pl);
    ((uint2*)g_Xkvh)[i] = ph;
    ((uint2*)g_Xkvl)[i] = pl;
}

// ---------------- depthwise 3x3, pad 1 — row-strip smem version -----------
__global__ __launch_bounds__(160) void dwconv3x3_v2(
    const float* __restrict__ X, const float* __restrict__ Wd,
    float* __restrict__ Y, int C)
{
    __shared__ float s[10][WIDTH];
    const int b = blockIdx.z, ch = blockIdx.y;
    const int r0 = blockIdx.x * 8;
    const int w = threadIdx.x;
    const float* xp = X + ((size_t)b * C + ch) * HW;
    #pragma unroll
    for (int i = 0; i < 10; i++) {
        int r = r0 - 1 + i;
        s[i][w] = (r >= 0 && r < WIDTH) ? xp[r * WIDTH + w] : 0.f;
    }
    const float* wp = Wd + ch * 9;
    float c00 = wp[0], c01 = wp[1], c02 = wp[2];
    float c10 = wp[3], c11 = wp[4], c12 = wp[5];
    float c20 = wp[6], c21 = wp[7], c22 = wp[8];
    __syncthreads();
    const bool wl = (w > 0), wr = (w < WIDTH - 1);
    float* yp = Y + ((size_t)b * C + ch) * HW + r0 * WIDTH + w;
    #pragma unroll
    for (int r = 0; r < 8; r++) {
        float a0 = wl ? s[r][w-1] : 0.f, a1 = s[r][w],   a2 = wr ? s[r][w+1] : 0.f;
        float b0 = wl ? s[r+1][w-1] : 0.f, b1 = s[r+1][w], b2 = wr ? s[r+1][w+1] : 0.f;
        float d0 = wl ? s[r+2][w-1] : 0.f, d1 = s[r+2][w], d2 = wr ? s[r+2][w+1] : 0.f;
        yp[r * WIDTH] = c00*a0 + c01*a1 + c02*a2
                      + c10*b0 + c11*b1 + c12*b2
                      + c20*d0 + c21*d1 + c22*d2;
    }
}

// ---- depthwise 3x3 for v: fp32 in (KVDIM stride) -> bf16 hi/lo out -------
__global__ __launch_bounds__(160) void dwconv3x3_vsplit(
    const float* __restrict__ X, const float* __restrict__ Wd,
    __nv_bfloat16* __restrict__ Yh, __nv_bfloat16* __restrict__ Yl)
{
    __shared__ float s[10][WIDTH];
    const int b = blockIdx.z, ch = blockIdx.y;
    const int r0 = blockIdx.x * 8;
    const int w = threadIdx.x;
    const float* xp = X + ((size_t)b * KVDIM + ch) * HW;    // X pre-offset to v half
    #pragma unroll
    for (int i = 0; i < 10; i++) {
        int r = r0 - 1 + i;
        s[i][w] = (r >= 0 && r < WIDTH) ? xp[r * WIDTH + w] : 0.f;
    }
    const float* wp = Wd + ch * 9;
    float c00 = wp[0], c01 = wp[1], c02 = wp[2];
    float c10 = wp[3], c11 = wp[4], c12 = wp[5];
    float c20 = wp[6], c21 = wp[7], c22 = wp[8];
    __syncthreads();
    const bool wl = (w > 0), wr = (w < WIDTH - 1);
    size_t base = ((size_t)b * CDIM + ch) * HW + r0 * WIDTH + w;
    #pragma unroll
    for (int r = 0; r < 8; r++) {
        float a0 = wl ? s[r][w-1] : 0.f, a1 = s[r][w],   a2 = wr ? s[r][w+1] : 0.f;
        float b0 = wl ? s[r+1][w-1] : 0.f, b1 = s[r+1][w], b2 = wr ? s[r+1][w+1] : 0.f;
        float d0 = wl ? s[r+2][w-1] : 0.f, d1 = s[r+2][w], d2 = wr ? s[r+2][w+1] : 0.f;
        float acc = c00*a0 + c01*a1 + c02*a2
                  + c10*b0 + c11*b1 + c12*b2
                  + c20*d0 + c21*d1 + c22*d2;
        __nv_bfloat16 hh = __float2bfloat16(acc);
        Yh[base + r * WIDTH] = hh;
        Yl[base + r * WIDTH] = __float2bfloat16(acc - __bfloat162float(hh));
    }
}

// ---------------- zero the gram accumulators -------------------------------
__global__ void zero_acc() {
    int i = blockIdx.x * 256 + threadIdx.x;
    const int nS = BATCH * HEADS * CPH * CPH;
    const int nN = BATCH * HEADS * CPH;
    if (i < nS) g_S[i] = 0.f;
    if (i < nN) { g_NQ[i] = 0.f; g_NK[i] = 0.f; }
}

// ---------------- Gram: S[b,h,c,d] = sum_n q[c,n] k[d,n]; plus sum q^2, k^2
__global__ __launch_bounds__(256) void gram(
    const float* __restrict__ Q, const float* __restrict__ K)
{
    __shared__ float qs[32][33];
    __shared__ float ks[32][33];
    const int b = blockIdx.z, hh = blockIdx.y, split = blockIdx.x;
    const int tid = threadIdx.x;
    const float* qb = Q + ((size_t)b * CDIM  + hh * CPH) * HW;
    const float* kb = K + ((size_t)b * KVDIM + hh * CPH) * HW;
    const int chunk = HW / NSPLIT;
    const int nbeg = split * chunk;
    const int ty = tid >> 4, tx = tid & 15;
    const int lc = tid >> 3;
    const int lj = (tid & 7) * 4;

    float acc00 = 0, acc01 = 0, acc10 = 0, acc11 = 0;
    float aq0 = 0, aq1 = 0, ak0 = 0, ak1 = 0;

    for (int n0 = nbeg; n0 < nbeg + chunk; n0 += 32) {
        float4 vq = *(const float4*)&qb[(size_t)lc * HW + n0 + lj];
        float4 vk = *(const float4*)&kb[(size_t)lc * HW + n0 + lj];
        qs[lc][lj] = vq.x; qs[lc][lj+1] = vq.y; qs[lc][lj+2] = vq.z; qs[lc][lj+3] = vq.w;
        ks[lc][lj] = vk.x; ks[lc][lj+1] = vk.y; ks[lc][lj+2] = vk.z; ks[lc][lj+3] = vk.w;
        __syncthreads();
        #pragma unroll
        for (int t = 0; t < 32; t++) {
            float q0 = qs[ty*2][t],  q1 = qs[ty*2+1][t];
            float k0 = ks[tx*2][t],  k1 = ks[tx*2+1][t];
            acc00 += q0*k0; acc01 += q0*k1; acc10 += q1*k0; acc11 += q1*k1;
            if (tx == 0) { aq0 += q0*q0; aq1 += q1*q1; }
            if (ty == 0) { ak0 += k0*k0; ak1 += k1*k1; }
        }
        __syncthreads();
    }
    float* Sb = g_S + (size_t)(b * HEADS + hh) * CPH * CPH;
    atomicAdd(&Sb[(ty*2    ) * CPH + tx*2    ], acc00);
    atomicAdd(&Sb[(ty*2    ) * CPH + tx*2 + 1], acc01);
    atomicAdd(&Sb[(ty*2 + 1) * CPH + tx*2    ], acc10);
    atomicAdd(&Sb[(ty*2 + 1) * CPH + tx*2 + 1], acc11);
    if (tx == 0) {
        atomicAdd(&g_NQ[(b * HEADS + hh) * CPH + ty*2    ], aq0);
        atomicAdd(&g_NQ[(b * HEADS + hh) * CPH + ty*2 + 1], aq1);
    }
    if (ty == 0) {
        atomicAdd(&g_NK[(b * HEADS + hh) * CPH + tx*2    ], ak0);
        atomicAdd(&g_NK[(b * HEADS + hh) * CPH + tx*2 + 1], ak1);
    }
}

// ---------------- softmax over d with L2-norm scaling + temperature --------
__global__ void softmax_attn(const float* __restrict__ temp) {
    const int bh = blockIdx.x;
    const int h  = bh % HEADS;
    const int d  = threadIdx.x;
    const float t = temp[h];
    float nk = fmaxf(sqrtf(g_NK[bh * CPH + d]), 1e-12f);
    for (int c = 0; c < CPH; c++) {
        float nq = fmaxf(sqrtf(g_NQ[bh * CPH + c]), 1e-12f);
        float v = g_S[bh * CPH * CPH + c * CPH + d] / (nq * nk) * t;
        float m = v;
        #pragma unroll
        for (int o = 16; o; o >>= 1) m = fmaxf(m, __shfl_xor_sync(~0u, m, o));
        float e = __expf(v - m);
        float s = e;
        #pragma unroll
        for (int o = 16; o; o >>= 1) s += __shfl_xor_sync(~0u, s, o);
        g_A[bh * CPH * CPH + c * CPH + d] = e / s;
    }
}

// ---------------- fold: M[b,o,g] = sum_c Wout[o, h*32+c] * A[b,h,c,d] ------
__global__ __launch_bounds__(256) void foldM(const float* __restrict__ Wout) {
    const int b = blockIdx.y;
    const int idx = blockIdx.x * 256 + threadIdx.x;
    const int o = idx / CDIM, g = idx % CDIM;
    const int h = g / CPH, d = g % CPH;
    const float* Ab = g_A + (size_t)(b * HEADS + h) * CPH * CPH;
    float acc = 0.f;
    #pragma unroll
    for (int c = 0; c < CPH; c++)
        acc += Wout[o * CDIM + h * CPH + c] * Ab[c * CPH + d];
    __nv_bfloat16 hh = __float2bfloat16(acc);
    g_Mh[(size_t)b * CDIM * CDIM + idx] = hh;
    g_Ml[(size_t)b * CDIM * CDIM + idx] = __float2bfloat16(acc - __bfloat162float(hh));
}

// ---------------- launch --------------------------------------------------
extern "C" void kernel_launch(void* const* d_in, const int* in_sizes, int n_in,
                              void* d_out, int out_size)
{
    const float* x_q   = (const float*)d_in[0];
    const float* x_kv  = (const float*)d_in[1];
    const float* w_q   = (const float*)d_in[2];
    const float* w_kv  = (const float*)d_in[3];
    const float* w_qdw = (const float*)d_in[4];
    const float* w_kvdw= (const float*)d_in[5];
    const float* w_out = (const float*)d_in[6];
    const float* temp  = (const float*)d_in[7];
    float* out = (float*)d_out;

    float *bq, *bkv, *bqd, *bkvd;
    __nv_bfloat16 *wqh, *wql, *wkvh, *wkvl, *mh, *ml;
    __nv_bfloat16 *xqh, *xql, *xkvh, *xkvl, *vh, *vl;
    cudaGetSymbolAddress((void**)&bq,   g_q);
    cudaGetSymbolAddress((void**)&bkv,  g_kv);
    cudaGetSymbolAddress((void**)&bqd,  g_qd);
    cudaGetSymbolAddress((void**)&bkvd, g_kvd);
    cudaGetSymbolAddress((void**)&wqh,  g_Wqh);
    cudaGetSymbolAddress((void**)&wql,  g_Wql);
    cudaGetSymbolAddress((void**)&wkvh, g_Wkvh);
    cudaGetSymbolAddress((void**)&wkvl, g_Wkvl);
    cudaGetSymbolAddress((void**)&mh,   g_Mh);
    cudaGetSymbolAddress((void**)&ml,   g_Ml);
    cudaGetSymbolAddress((void**)&xqh,  g_Xqh);
    cudaGetSymbolAddress((void**)&xql,  g_Xql);
    cudaGetSymbolAddress((void**)&xkvh, g_Xkvh);
    cudaGetSymbolAddress((void**)&xkvl, g_Xkvl);
    cudaGetSymbolAddress((void**)&vh,   g_Vh);
    cudaGetSymbolAddress((void**)&vl,   g_Vl);

    cudaFuncSetAttribute(gemm_bf16, cudaFuncAttributeMaxDynamicSharedMemorySize, SM_TOTAL);

    // 0) split weights + activations to bf16 hi/lo (both x tensors are 192-ch)
    split_w<<<(KVDIM * CDIM + 255) / 256, 256>>>(w_q, w_kv);
    split_x<<<(int)(((size_t)BATCH * CDIM * HW / 4) / 256), 256>>>(x_q, x_kv);
    // 1) q = W_q @ x_q         (K contraction dim = CDIM)
    gemm_bf16<<<dim3(HW/128, CDIM/64, BATCH), 256, SM_TOTAL>>>(
        wqh, wql, xqh, xql, bq, CDIM, 0, (long)CDIM * HW);
    // 2) kv = W_kv @ x_kv (384 outputs; input batch stride = CDIM*HW)
    gemm_bf16<<<dim3(HW/128, KVDIM/64, BATCH), 256, SM_TOTAL>>>(
        wkvh, wkvl, xkvh, xkvl, bkv, KVDIM, 0, (long)CDIM * HW);
    // 3) depthwise 3x3: q (fp32), k (fp32, first half of kv), v (bf16 split)
    dwconv3x3_v2<<<dim3(WIDTH/8, CDIM, BATCH), WIDTH>>>(bq, w_qdw, bqd, CDIM);
    dwconv3x3_v2<<<dim3(WIDTH/8, CDIM, BATCH), WIDTH>>>(bkv, w_kvdw, bkvd, KVDIM);
    dwconv3x3_vsplit<<<dim3(WIDTH/8, CDIM, BATCH), WIDTH>>>(
        bkv + (size_t)CDIM * HW, w_kvdw + CDIM * 9, vh, vl);
    // 4) zero gram accumulators
    zero_acc<<<(BATCH*HEADS*CPH*CPH + 255)/256, 256>>>();
    // 5) gram + norms (k = first KVDIM-strided half of kvd)
    gram<<<dim3(NSPLIT, HEADS, BATCH), 256>>>(bqd, bkvd);
    // 6) softmax with normalization + temperature
    softmax_attn<<<BATCH * HEADS, 32>>>(temp);
    // 7) fold W_out with attention -> bf16 hi/lo M
    foldM<<<dim3(CDIM*CDIM/256, BATCH), 256>>>(w_out);
    // 8) out = M_b @ v
    gemm_bf16<<<dim3(HW/128, CDIM/64, BATCH), 256, SM_TOTAL>>>(
        mh, ml, vh, vl, out, CDIM, (long)CDIM * CDIM, (long)CDIM * HW);
}

// round 15
// speedup vs baseline: 1.5512x; 1.4191x over previous
#include <cuda_runtime.h>
#include <cuda_bf16.h>
#include <cuda_fp16.h>
#include <math.h>
#include <stdint.h>

#define CDIM   192
#define KVDIM  384
#define HEADS  6
#define CPH    32
#define WIDTH  160
#define HW     25600          // 160*160
#define BATCH  8
#define NSPLIT 16

// ---------------- scratch (device globals; no allocation) ----------------
__device__ float g_q   [(size_t)BATCH * CDIM  * HW];   // q after 1x1
__device__ float g_kv  [(size_t)BATCH * KVDIM * HW];   // kv after 1x1
__device__ float g_qd  [(size_t)BATCH * CDIM  * HW];   // q after dw3x3
__device__ float g_kvd [(size_t)BATCH * KVDIM * HW];   // k after dw3x3 (first half used)
__device__ float g_S   [BATCH * HEADS * CPH * CPH];    // raw gram
__device__ float g_NQ  [BATCH * HEADS * CPH];          // sum q^2
__device__ float g_NK  [BATCH * HEADS * CPH];          // sum k^2
__device__ float g_A   [BATCH * HEADS * CPH * CPH];    // softmax(attn)
// fp16 operands for tensor-core GEMMs
__device__ __half g_Wq16 [CDIM  * CDIM];
__device__ __half g_Wkv16[KVDIM * CDIM];
__device__ __half g_M16  [BATCH * CDIM * CDIM];        // W_out @ blockdiag(A)
__device__ __half g_Xq16 [(size_t)BATCH * CDIM * HW];  // x_query
__device__ __half g_Xkv16[(size_t)BATCH * CDIM * HW];  // x_key_value (192 ch)
__device__ __half g_V16  [(size_t)BATCH * CDIM * HW];  // v after dw3x3

// ================= warp-MMA + cp.async helpers (arch-agnostic PTX) ========
__device__ __forceinline__ uint32_t smem_u32(const void* p) {
    uint32_t a;
    asm("{ .reg .u64 t; cvta.to.shared.u64 t, %1; cvt.u32.u64 %0, t; }" : "=r"(a) : "l"(p));
    return a;
}
__device__ __forceinline__ void ldsm_x4(uint32_t (&r)[4], uint32_t addr) {
    asm volatile("ldmatrix.sync.aligned.m8n8.x4.shared.b16 {%0,%1,%2,%3}, [%4];"
        : "=r"(r[0]), "=r"(r[1]), "=r"(r[2]), "=r"(r[3]) : "r"(addr));
}
__device__ __forceinline__ void ldsm_x4_t(uint32_t (&r)[4], uint32_t addr) {
    asm volatile("ldmatrix.sync.aligned.m8n8.x4.trans.shared.b16 {%0,%1,%2,%3}, [%4];"
        : "=r"(r[0]), "=r"(r[1]), "=r"(r[2]), "=r"(r[3]) : "r"(addr));
}
__device__ __forceinline__ void mma_fp16(float (&d)[4], const uint32_t (&a)[4],
                                         uint32_t b0, uint32_t b1) {
    asm volatile("mma.sync.aligned.m16n8k16.row.col.f32.f16.f16.f32 "
        "{%0,%1,%2,%3}, {%4,%5,%6,%7}, {%8,%9}, {%0,%1,%2,%3};"
        : "+f"(d[0]), "+f"(d[1]), "+f"(d[2]), "+f"(d[3])
        : "r"(a[0]), "r"(a[1]), "r"(a[2]), "r"(a[3]), "r"(b0), "r"(b1));
}
#define CP16(dst, src) \
    asm volatile("cp.async.cg.shared.global [%0], [%1], 16;" :: "r"(dst), "l"(src))
#define CP_COMMIT() asm volatile("cp.async.commit_group;" ::: "memory")
#define CP_WAIT1()  asm volatile("cp.async.wait_group 1;" ::: "memory")
#define CP_WAIT0()  asm volatile("cp.async.wait_group 0;" ::: "memory")

// ============ fp16 tensor-core GEMM, 3-stage cp.async ring ================
// Y[(b*O + o0+m)*HW + n0+n] = sum_k A[o0+m][k] * B[b][k][n0+n]
// BM=64, BN=128, BK=32; 256 thr = 2x4 warps; warp = 32m x 32n. K = 192.
#define APAD 40     // A row = 80 B (16B-aligned, ldmatrix conflict-free)
#define BPAD 136    // B row = 272 B
#define A_SZ 5120   // 64*40*2
#define B_SZ 8704   // 32*136*2
#define SM_TOTAL (3*A_SZ + 3*B_SZ)   // 41472 B
__device__ __forceinline__ uint32_t aOff(int s) { return (uint32_t)s * A_SZ; }
__device__ __forceinline__ uint32_t bOff(int s) { return 3*A_SZ + (uint32_t)s * B_SZ; }

__global__ __launch_bounds__(256, 3) void gemm_fp16(
    const __half* __restrict__ Ax, const __half* __restrict__ Bx,
    float* __restrict__ Y, int O, long wBatch, long xBatch)
{
    extern __shared__ char smem[];
    const uint32_t sb = smem_u32(smem);

    const int tid  = threadIdx.x;
    const int wid  = tid >> 5, lane = tid & 31;
    const int wm   = wid >> 2;          // 0..1
    const int wn   = wid & 3;           // 0..3
    const int n0   = blockIdx.x * 128;
    const int o0   = blockIdx.y * 64;
    const int b    = blockIdx.z;

    const __half* Ab = Ax + (size_t)b * wBatch + (size_t)o0 * CDIM;
    const __half* Bb = Bx + (size_t)b * xBatch + n0;

    // staging coords (16B chunks): A 256 chunks (1/thr), B 512 chunks (2/thr)
    const int am = tid >> 2, ak = (tid & 3) * 8;
    const int bk0c = tid >> 4, bn0c = (tid & 15) * 8;
    const int bk1c = (tid + 256) >> 4, bn1c = ((tid + 256) & 15) * 8;

    // ldmatrix coords
    const int aRow = (lane & 7) + ((lane >> 3) & 1) * 8;
    const int aCol = ((lane >> 4) & 1) * 8;
    const int bRow = aRow, bCol = aCol;

    float acc[2][4][4] = {};

    // ---- prologue: stage kb=0 -> stage0, kb=1 -> stage1 ----
    #pragma unroll
    for (int p = 0; p < 2; p++) {
        const int k0 = p * 32;
        CP16(sb + aOff(p) + (am*APAD + ak)*2, Ab + (size_t)am * CDIM + k0 + ak);
        CP16(sb + bOff(p) + (bk0c*BPAD + bn0c)*2, Bb + (size_t)(k0 + bk0c) * HW + bn0c);
        CP16(sb + bOff(p) + (bk1c*BPAD + bn1c)*2, Bb + (size_t)(k0 + bk1c) * HW + bn1c);
        CP_COMMIT();
    }

    #pragma unroll 1
    for (int kb = 0; kb < 6; kb++) {
        if (kb < 5) CP_WAIT1(); else CP_WAIT0();   // group kb complete
        __syncthreads();                            // visible to all; prev reads done
        if (kb + 2 < 6) {                           // stage kb+2 into ring slot
            const int s = (kb + 2) % 3;
            const int k0 = (kb + 2) * 32;
            CP16(sb + aOff(s) + (am*APAD + ak)*2, Ab + (size_t)am * CDIM + k0 + ak);
            CP16(sb + bOff(s) + (bk0c*BPAD + bn0c)*2, Bb + (size_t)(k0 + bk0c) * HW + bn0c);
            CP16(sb + bOff(s) + (bk1c*BPAD + bn1c)*2, Bb + (size_t)(k0 + bk1c) * HW + bn1c);
            CP_COMMIT();
        }
        const int cs = kb % 3;
        #pragma unroll
        for (int ks = 0; ks < 2; ks++) {
            uint32_t ah[2][4], bh[2][4];
            #pragma unroll
            for (int mt = 0; mt < 2; mt++) {
                uint32_t off = (uint32_t)((wm * 32 + mt * 16 + aRow) * APAD + ks * 16 + aCol) * 2;
                ldsm_x4(ah[mt], sb + aOff(cs) + off);
            }
            #pragma unroll
            for (int np = 0; np < 2; np++) {
                uint32_t off = (uint32_t)((ks * 16 + bRow) * BPAD + wn * 32 + np * 16 + bCol) * 2;
                ldsm_x4_t(bh[np], sb + bOff(cs) + off);
            }
            #pragma unroll
            for (int mt = 0; mt < 2; mt++)
                #pragma unroll
                for (int np = 0; np < 2; np++)
                    #pragma unroll
                    for (int s = 0; s < 2; s++)
                        mma_fp16(acc[mt][np*2+s], ah[mt], bh[np][s*2], bh[np][s*2+1]);
        }
    }

    // ---- epilogue ----
    const int g = lane >> 2, cc = (lane & 3) * 2;
    #pragma unroll
    for (int mt = 0; mt < 2; mt++) {
        #pragma unroll
        for (int nt = 0; nt < 4; nt++) {
            int orow = o0 + wm * 32 + mt * 16 + g;
            int ncol = n0 + wn * 32 + nt * 8 + cc;
            float2 v0 = make_float2(acc[mt][nt][0], acc[mt][nt][1]);
            float2 v1 = make_float2(acc[mt][nt][2], acc[mt][nt][3]);
            *(float2*)&Y[((size_t)b * O + orow    ) * HW + ncol] = v0;
            *(float2*)&Y[((size_t)b * O + orow + 8) * HW + ncol] = v1;
        }
    }
}

// ---------------- convert fp32 weights to fp16 ----------------------------
__global__ void convert_w(const float* __restrict__ wq, const float* __restrict__ wkv) {
    int i = blockIdx.x * 256 + threadIdx.x;
    if (i < CDIM * CDIM)  g_Wq16[i]  = __float2half_rn(wq[i]);
    if (i < KVDIM * CDIM) g_Wkv16[i] = __float2half_rn(wkv[i]);
}

// ---------------- convert fp32 activations to fp16 ------------------------
__global__ __launch_bounds__(256) void convert_x(
    const float* __restrict__ xq, const float* __restrict__ xkv)
{
    const size_t i = (size_t)blockIdx.x * 256 + threadIdx.x;      // float4 index
    float4 v = ((const float4*)xq)[i];
    __half2 a = __floats2half2_rn(v.x, v.y);
    __half2 b = __floats2half2_rn(v.z, v.w);
    ((uint2*)g_Xq16)[i] = make_uint2(*(uint32_t*)&a, *(uint32_t*)&b);
    v = ((const float4*)xkv)[i];
    a = __floats2half2_rn(v.x, v.y);
    b = __floats2half2_rn(v.z, v.w);
    ((uint2*)g_Xkv16)[i] = make_uint2(*(uint32_t*)&a, *(uint32_t*)&b);
}

// ---------------- depthwise 3x3, pad 1 — row-strip smem version -----------
__global__ __launch_bounds__(160) void dwconv3x3_v2(
    const float* __restrict__ X, const float* __restrict__ Wd,
    float* __restrict__ Y, int C)
{
    __shared__ float s[10][WIDTH];
    const int b = blockIdx.z, ch = blockIdx.y;
    const int r0 = blockIdx.x * 8;
    const int w = threadIdx.x;
    const float* xp = X + ((size_t)b * C + ch) * HW;
    #pragma unroll
    for (int i = 0; i < 10; i++) {
        int r = r0 - 1 + i;
        s[i][w] = (r >= 0 && r < WIDTH) ? xp[r * WIDTH + w] : 0.f;
    }
    const float* wp = Wd + ch * 9;
    float c00 = wp[0], c01 = wp[1], c02 = wp[2];
    float c10 = wp[3], c11 = wp[4], c12 = wp[5];
    float c20 = wp[6], c21 = wp[7], c22 = wp[8];
    __syncthreads();
    const bool wl = (w > 0), wr = (w < WIDTH - 1);
    float* yp = Y + ((size_t)b * C + ch) * HW + r0 * WIDTH + w;
    #pragma unroll
    for (int r = 0; r < 8; r++) {
        float a0 = wl ? s[r][w-1] : 0.f, a1 = s[r][w],   a2 = wr ? s[r][w+1] : 0.f;
        float b0 = wl ? s[r+1][w-1] : 0.f, b1 = s[r+1][w], b2 = wr ? s[r+1][w+1] : 0.f;
        float d0 = wl ? s[r+2][w-1] : 0.f, d1 = s[r+2][w], d2 = wr ? s[r+2][w+1] : 0.f;
        yp[r * WIDTH] = c00*a0 + c01*a1 + c02*a2
                      + c10*b0 + c11*b1 + c12*b2
                      + c20*d0 + c21*d1 + c22*d2;
    }
}

// ---- depthwise 3x3 for v: fp32 in (KVDIM stride) -> fp16 out -------------
__global__ __launch_bounds__(160) void dwconv3x3_vh(
    const float* __restrict__ X, const float* __restrict__ Wd,
    __half* __restrict__ Yh)
{
    __shared__ float s[10][WIDTH];
    const int b = blockIdx.z, ch = blockIdx.y;
    const int r0 = blockIdx.x * 8;
    const int w = threadIdx.x;
    const float* xp = X + ((size_t)b * KVDIM + ch) * HW;    // X pre-offset to v half
    #pragma unroll
    for (int i = 0; i < 10; i++) {
        int r = r0 - 1 + i;
        s[i][w] = (r >= 0 && r < WIDTH) ? xp[r * WIDTH + w] : 0.f;
    }
    const float* wp = Wd + ch * 9;
    float c00 = wp[0], c01 = wp[1], c02 = wp[2];
    float c10 = wp[3], c11 = wp[4], c12 = wp[5];
    float c20 = wp[6], c21 = wp[7], c22 = wp[8];
    __syncthreads();
    const bool wl = (w > 0), wr = (w < WIDTH - 1);
    size_t base = ((size_t)b * CDIM + ch) * HW + r0 * WIDTH + w;
    #pragma unroll
    for (int r = 0; r < 8; r++) {
        float a0 = wl ? s[r][w-1] : 0.f, a1 = s[r][w],   a2 = wr ? s[r][w+1] : 0.f;
        float b0 = wl ? s[r+1][w-1] : 0.f, b1 = s[r+1][w], b2 = wr ? s[r+1][w+1] : 0.f;
        float d0 = wl ? s[r+2][w-1] : 0.f, d1 = s[r+2][w], d2 = wr ? s[r+2][w+1] : 0.f;
        float acc = c00*a0 + c01*a1 + c02*a2
                  + c10*b0 + c11*b1 + c12*b2
                  + c20*d0 + c21*d1 + c22*d2;
        Yh[base + r * WIDTH] = __float2half_rn(acc);
    }
}

// ---------------- zero the gram accumulators -------------------------------
__global__ void zero_acc() {
    int i = blockIdx.x * 256 + threadIdx.x;
    const int nS = BATCH * HEADS * CPH * CPH;
    const int nN = BATCH * HEADS * CPH;
    if (i < nS) g_S[i] = 0.f;
    if (i < nN) { g_NQ[i] = 0.f; g_NK[i] = 0.f; }
}

// ---------------- Gram: S[b,h,c,d] = sum_n q[c,n] k[d,n]; plus sum q^2, k^2
__global__ __launch_bounds__(256) void gram(
    const float* __restrict__ Q, const float* __restrict__ K)
{
    __shared__ float qs[32][33];
    __shared__ float ks[32][33];
    const int b = blockIdx.z, hh = blockIdx.y, split = blockIdx.x;
    const int tid = threadIdx.x;
    const float* qb = Q + ((size_t)b * CDIM  + hh * CPH) * HW;
    const float* kb = K + ((size_t)b * KVDIM + hh * CPH) * HW;
    const int chunk = HW / NSPLIT;
    const int nbeg = split * chunk;
    const int ty = tid >> 4, tx = tid & 15;
    const int lc = tid >> 3;
    const int lj = (tid & 7) * 4;

    float acc00 = 0, acc01 = 0, acc10 = 0, acc11 = 0;
    float aq0 = 0, aq1 = 0, ak0 = 0, ak1 = 0;

    for (int n0 = nbeg; n0 < nbeg + chunk; n0 += 32) {
        float4 vq = *(const float4*)&qb[(size_t)lc * HW + n0 + lj];
        float4 vk = *(const float4*)&kb[(size_t)lc * HW + n0 + lj];
        qs[lc][lj] = vq.x; qs[lc][lj+1] = vq.y; qs[lc][lj+2] = vq.z; qs[lc][lj+3] = vq.w;
        ks[lc][lj] = vk.x; ks[lc][lj+1] = vk.y; ks[lc][lj+2] = vk.z; ks[lc][lj+3] = vk.w;
        __syncthreads();
        #pragma unroll
        for (int t = 0; t < 32; t++) {
            float q0 = qs[ty*2][t],  q1 = qs[ty*2+1][t];
            float k0 = ks[tx*2][t],  k1 = ks[tx*2+1][t];
            acc00 += q0*k0; acc01 += q0*k1; acc10 += q1*k0; acc11 += q1*k1;
            if (tx == 0) { aq0 += q0*q0; aq1 += q1*q1; }
            if (ty == 0) { ak0 += k0*k0; ak1 += k1*k1; }
        }
        __syncthreads();
    }
    float* Sb = g_S + (size_t)(b * HEADS + hh) * CPH * CPH;
    atomicAdd(&Sb[(ty*2    ) * CPH + tx*2    ], acc00);
    atomicAdd(&Sb[(ty*2    ) * CPH + tx*2 + 1], acc01);
    atomicAdd(&Sb[(ty*2 + 1) * CPH + tx*2    ], acc10);
    atomicAdd(&Sb[(ty*2 + 1) * CPH + tx*2 + 1], acc11);
    if (tx == 0) {
        atomicAdd(&g_NQ[(b * HEADS + hh) * CPH + ty*2    ], aq0);
        atomicAdd(&g_NQ[(b * HEADS + hh) * CPH + ty*2 + 1], aq1);
    }
    if (ty == 0) {
        atomicAdd(&g_NK[(b * HEADS + hh) * CPH + tx*2    ], ak0);
        atomicAdd(&g_NK[(b * HEADS + hh) * CPH + tx*2 + 1], ak1);
    }
}

// ---------------- softmax over d with L2-norm scaling + temperature --------
__global__ void softmax_attn(const float* __restrict__ temp) {
    const int bh = blockIdx.x;
    const int h  = bh % HEADS;
    const int d  = threadIdx.x;
    const float t = temp[h];
    float nk = fmaxf(sqrtf(g_NK[bh * CPH + d]), 1e-12f);
    for (int c = 0; c < CPH; c++) {
        float nq = fmaxf(sqrtf(g_NQ[bh * CPH + c]), 1e-12f);
        float v = g_S[bh * CPH * CPH + c * CPH + d] / (nq * nk) * t;
        float m = v;
        #pragma unroll
        for (int o = 16; o; o >>= 1) m = fmaxf(m, __shfl_xor_sync(~0u, m, o));
        float e = __expf(v - m);
        float s = e;
        #pragma unroll
        for (int o = 16; o; o >>= 1) s += __shfl_xor_sync(~0u, s, o);
        g_A[bh * CPH * CPH + c * CPH + d] = e / s;
    }
}

// ---------------- fold: M[b,o,g] = sum_c Wout[o, h*32+c] * A[b,h,c,d] ------
__global__ __launch_bounds__(256) void foldM(const float* __restrict__ Wout) {
    const int b = blockIdx.y;
    const int idx = blockIdx.x * 256 + threadIdx.x;
    const int o = idx / CDIM, g = idx % CDIM;
    const int h = g / CPH, d = g % CPH;
    const float* Ab = g_A + (size_t)(b * HEADS + h) * CPH * CPH;
    float acc = 0.f;
    #pragma unroll
    for (int c = 0; c < CPH; c++)
        acc += Wout[o * CDIM + h * CPH + c] * Ab[c * CPH + d];
    g_M16[(size_t)b * CDIM * CDIM + idx] = __float2half_rn(acc);
}

// ---------------- launch --------------------------------------------------
extern "C" void kernel_launch(void* const* d_in, const int* in_sizes, int n_in,
                              void* d_out, int out_size)
{
    const float* x_q   = (const float*)d_in[0];
    const float* x_kv  = (const float*)d_in[1];
    const float* w_q   = (const float*)d_in[2];
    const float* w_kv  = (const float*)d_in[3];
    const float* w_qdw = (const float*)d_in[4];
    const float* w_kvdw= (const float*)d_in[5];
    const float* w_out = (const float*)d_in[6];
    const float* temp  = (const float*)d_in[7];
    float* out = (float*)d_out;

    float *bq, *bkv, *bqd, *bkvd;
    __half *wq16, *wkv16, *m16, *xq16, *xkv16, *v16;
    cudaGetSymbolAddress((void**)&bq,    g_q);
    cudaGetSymbolAddress((void**)&bkv,   g_kv);
    cudaGetSymbolAddress((void**)&bqd,   g_qd);
    cudaGetSymbolAddress((void**)&bkvd,  g_kvd);
    cudaGetSymbolAddress((void**)&wq16,  g_Wq16);
    cudaGetSymbolAddress((void**)&wkv16, g_Wkv16);
    cudaGetSymbolAddress((void**)&m16,   g_M16);
    cudaGetSymbolAddress((void**)&xq16,  g_Xq16);
    cudaGetSymbolAddress((void**)&xkv16, g_Xkv16);
    cudaGetSymbolAddress((void**)&v16,   g_V16);

    cudaFuncSetAttribute(gemm_fp16, cudaFuncAttributeMaxDynamicSharedMemorySize, SM_TOTAL);

    // 0) convert weights + activations to fp16
    convert_w<<<(KVDIM * CDIM + 255) / 256, 256>>>(w_q, w_kv);
    convert_x<<<(int)(((size_t)BATCH * CDIM * HW / 4) / 256), 256>>>(x_q, x_kv);
    // 1) q = W_q @ x_q
    gemm_fp16<<<dim3(HW/128, CDIM/64, BATCH), 256, SM_TOTAL>>>(
        wq16, xq16, bq, CDIM, 0, (long)CDIM * HW);
    // 2) kv = W_kv @ x_kv (384 outputs)
    gemm_fp16<<<dim3(HW/128, KVDIM/64, BATCH), 256, SM_TOTAL>>>(
        wkv16, xkv16, bkv, KVDIM, 0, (long)CDIM * HW);
    // 3) depthwise 3x3: q (fp32), k (fp32, first half of kv), v (fp16 out)
    dwconv3x3_v2<<<dim3(WIDTH/8, CDIM, BATCH), WIDTH>>>(bq, w_qdw, bqd, CDIM);
    dwconv3x3_v2<<<dim3(WIDTH/8, CDIM, BATCH), WIDTH>>>(bkv, w_kvdw, bkvd, KVDIM);
    dwconv3x3_vh<<<dim3(WIDTH/8, CDIM, BATCH), WIDTH>>>(
        bkv + (size_t)CDIM * HW, w_kvdw + CDIM * 9, v16);
    // 4) zero gram accumulators
    zero_acc<<<(BATCH*HEADS*CPH*CPH + 255)/256, 256>>>();
    // 5) gram + norms (k = first KVDIM-strided half of kvd)
    gram<<<dim3(NSPLIT, HEADS, BATCH), 256>>>(bqd, bkvd);
    // 6) softmax with normalization + temperature
    softmax_attn<<<BATCH * HEADS, 32>>>(temp);
    // 7) fold W_out with attention -> fp16 M
    foldM<<<dim3(CDIM*CDIM/256, BATCH), 256>>>(w_out);
    // 8) out = M_b @ v
    gemm_fp16<<<dim3(HW/128, CDIM/64, BATCH), 256, SM_TOTAL>>>(
        m16, v16, out, CDIM, (long)CDIM * CDIM, (long)CDIM * HW);
}

// round 16
// speedup vs baseline: 1.5842x; 1.0212x over previous
#include <cuda_runtime.h>
#include <cuda_bf16.h>
#include <cuda_fp16.h>
#include <math.h>
#include <stdint.h>

#define CDIM   192
#define KVDIM  384
#define HEADS  6
#define CPH    32
#define WIDTH  160
#define HW     25600          // 160*160
#define BATCH  8
#define NSPLIT 16

// ---------------- scratch (device globals; no allocation) ----------------
__device__ float g_q   [(size_t)BATCH * CDIM  * HW];   // q after 1x1
__device__ float g_kv  [(size_t)BATCH * KVDIM * HW];   // kv after 1x1
__device__ float g_qd  [(size_t)BATCH * CDIM  * HW];   // q after dw3x3
__device__ float g_kvd [(size_t)BATCH * KVDIM * HW];   // k after dw3x3 (first half used)
__device__ float g_S   [BATCH * HEADS * CPH * CPH];    // raw gram
__device__ float g_NQ  [BATCH * HEADS * CPH];          // sum q^2
__device__ float g_NK  [BATCH * HEADS * CPH];          // sum k^2
__device__ float g_A   [BATCH * HEADS * CPH * CPH];    // softmax(attn)
// fp16 operands for tensor-core GEMMs
__device__ __half g_Wq16 [CDIM  * CDIM];
__device__ __half g_Wkv16[KVDIM * CDIM];
__device__ __half g_M16  [BATCH * CDIM * CDIM];        // W_out @ blockdiag(A)
__device__ __half g_Xq16 [(size_t)BATCH * CDIM * HW];  // x_query
__device__ __half g_Xkv16[(size_t)BATCH * CDIM * HW];  // x_key_value (192 ch)
__device__ __half g_V16  [(size_t)BATCH * CDIM * HW];  // v after dw3x3

// ================= warp-MMA + cp.async helpers (arch-agnostic PTX) ========
__device__ __forceinline__ uint32_t smem_u32(const void* p) {
    uint32_t a;
    asm("{ .reg .u64 t; cvta.to.shared.u64 t, %1; cvt.u32.u64 %0, t; }" : "=r"(a) : "l"(p));
    return a;
}
__device__ __forceinline__ void ldsm_x4(uint32_t (&r)[4], uint32_t addr) {
    asm volatile("ldmatrix.sync.aligned.m8n8.x4.shared.b16 {%0,%1,%2,%3}, [%4];"
        : "=r"(r[0]), "=r"(r[1]), "=r"(r[2]), "=r"(r[3]) : "r"(addr));
}
__device__ __forceinline__ void ldsm_x4_t(uint32_t (&r)[4], uint32_t addr) {
    asm volatile("ldmatrix.sync.aligned.m8n8.x4.trans.shared.b16 {%0,%1,%2,%3}, [%4];"
        : "=r"(r[0]), "=r"(r[1]), "=r"(r[2]), "=r"(r[3]) : "r"(addr));
}
__device__ __forceinline__ void mma_fp16(float (&d)[4], const uint32_t (&a)[4],
                                         uint32_t b0, uint32_t b1) {
    asm volatile("mma.sync.aligned.m16n8k16.row.col.f32.f16.f16.f32 "
        "{%0,%1,%2,%3}, {%4,%5,%6,%7}, {%8,%9}, {%0,%1,%2,%3};"
        : "+f"(d[0]), "+f"(d[1]), "+f"(d[2]), "+f"(d[3])
        : "r"(a[0]), "r"(a[1]), "r"(a[2]), "r"(a[3]), "r"(b0), "r"(b1));
}
#define CP16(dst, src) \
    asm volatile("cp.async.cg.shared.global [%0], [%1], 16;" :: "r"(dst), "l"(src))
#define CP_COMMIT() asm volatile("cp.async.commit_group;" ::: "memory")
#define CP_WAIT1()  asm volatile("cp.async.wait_group 1;" ::: "memory")
#define CP_WAIT0()  asm volatile("cp.async.wait_group 0;" ::: "memory")

// ============ fp16 tensor-core GEMM, BK=64, 2-stage double buffer =========
// Y[(b*O + o0+m)*HW + n0+n] = sum_k A[o0+m][k] * B[b][k][n0+n]
// BM=64, BN=128, BK=64; 256 thr = 2x4 warps; warp = 32m x 32n. K = 192.
#define APAD 72     // A row = 144 B (16B-aligned; 144%128=16 -> conflict-free ldsm)
#define BPAD 136    // B row = 272 B
#define A_SZ (64*APAD*2)      // 9216
#define B_SZ (64*BPAD*2)      // 17408
#define STG_SZ (A_SZ + B_SZ)  // 26624
#define SM_TOTAL (2*STG_SZ)   // 53248
__device__ __forceinline__ uint32_t aOff(int s) { return (uint32_t)s * STG_SZ; }
__device__ __forceinline__ uint32_t bOff(int s) { return (uint32_t)s * STG_SZ + A_SZ; }

__global__ __launch_bounds__(256, 3) void gemm_fp16(
    const __half* __restrict__ Ax, const __half* __restrict__ Bx,
    float* __restrict__ Y, int O, long wBatch, long xBatch)
{
    extern __shared__ char smem[];
    const uint32_t sb = smem_u32(smem);

    const int tid  = threadIdx.x;
    const int wid  = tid >> 5, lane = tid & 31;
    const int wm   = wid >> 2;          // 0..1
    const int wn   = wid & 3;           // 0..3
    const int n0   = blockIdx.x * 128;
    const int o0   = blockIdx.y * 64;
    const int b    = blockIdx.z;

    const __half* Ab = Ax + (size_t)b * wBatch + (size_t)o0 * CDIM;
    const __half* Bb = Bx + (size_t)b * xBatch + n0;

    // staging coords (16B chunks): A 512 chunks (2/thr), B 1024 chunks (4/thr)
    // A chunk c: m = c>>3 (8 chunks per 64-half row), k = (c&7)*8
    // B chunk c: k = c>>4 (16 chunks per 128-half row), n = (c&15)*8
    const int a0m = tid >> 3,          a0k = (tid & 7) * 8;
    const int a1m = (tid + 256) >> 3,  a1k = (tid & 7) * 8;   // (c&7) same for +256
    const int bkc[4] = { tid >> 4, (tid + 256) >> 4, (tid + 512) >> 4, (tid + 768) >> 4 };
    const int bnc    = (tid & 15) * 8;

    // ldmatrix coords
    const int aRow = (lane & 7) + ((lane >> 3) & 1) * 8;
    const int aCol = ((lane >> 4) & 1) * 8;
    const int bRow = aRow, bCol = aCol;

    float acc[2][4][4] = {};

    // ---- prologue: stage kb=0 into buf 0 ----
    {
        CP16(sb + aOff(0) + (a0m*APAD + a0k)*2, Ab + (size_t)a0m * CDIM + a0k);
        CP16(sb + aOff(0) + (a1m*APAD + a1k)*2, Ab + (size_t)a1m * CDIM + a1k);
        #pragma unroll
        for (int i = 0; i < 4; i++)
            CP16(sb + bOff(0) + (bkc[i]*BPAD + bnc)*2, Bb + (size_t)bkc[i] * HW + bnc);
        CP_COMMIT();
    }

    int buf = 0;
    #pragma unroll 1
    for (int kb = 0; kb < 3; kb++) {
        if (kb < 2) {                       // stage next 64-k block into other buffer
            const int k0 = (kb + 1) * 64;
            const int nb = buf ^ 1;
            CP16(sb + aOff(nb) + (a0m*APAD + a0k)*2, Ab + (size_t)a0m * CDIM + k0 + a0k);
            CP16(sb + aOff(nb) + (a1m*APAD + a1k)*2, Ab + (size_t)a1m * CDIM + k0 + a1k);
            #pragma unroll
            for (int i = 0; i < 4; i++)
                CP16(sb + bOff(nb) + (bkc[i]*BPAD + bnc)*2, Bb + (size_t)(k0 + bkc[i]) * HW + bnc);
            CP_COMMIT();
            CP_WAIT1();                      // current block's group done
        } else {
            CP_WAIT0();
        }
        __syncthreads();

        #pragma unroll
        for (int ks = 0; ks < 4; ks++) {
            uint32_t ah[2][4], bh[2][4];
            #pragma unroll
            for (int mt = 0; mt < 2; mt++) {
                uint32_t off = (uint32_t)((wm * 32 + mt * 16 + aRow) * APAD + ks * 16 + aCol) * 2;
                ldsm_x4(ah[mt], sb + aOff(buf) + off);
            }
            #pragma unroll
            for (int np = 0; np < 2; np++) {
                uint32_t off = (uint32_t)((ks * 16 + bRow) * BPAD + wn * 32 + np * 16 + bCol) * 2;
                ldsm_x4_t(bh[np], sb + bOff(buf) + off);
            }
            #pragma unroll
            for (int mt = 0; mt < 2; mt++)
                #pragma unroll
                for (int np = 0; np < 2; np++)
                    #pragma unroll
                    for (int s = 0; s < 2; s++)
                        mma_fp16(acc[mt][np*2+s], ah[mt], bh[np][s*2], bh[np][s*2+1]);
        }
        __syncthreads();                     // compute done before buf is overwritten
        buf ^= 1;
    }

    // ---- epilogue ----
    const int g = lane >> 2, cc = (lane & 3) * 2;
    #pragma unroll
    for (int mt = 0; mt < 2; mt++) {
        #pragma unroll
        for (int nt = 0; nt < 4; nt++) {
            int orow = o0 + wm * 32 + mt * 16 + g;
            int ncol = n0 + wn * 32 + nt * 8 + cc;
            float2 v0 = make_float2(acc[mt][nt][0], acc[mt][nt][1]);
            float2 v1 = make_float2(acc[mt][nt][2], acc[mt][nt][3]);
            *(float2*)&Y[((size_t)b * O + orow    ) * HW + ncol] = v0;
            *(float2*)&Y[((size_t)b * O + orow + 8) * HW + ncol] = v1;
        }
    }
}

// ---------------- convert fp32 weights to fp16 ----------------------------
__global__ void convert_w(const float* __restrict__ wq, const float* __restrict__ wkv) {
    int i = blockIdx.x * 256 + threadIdx.x;
    if (i < CDIM * CDIM)  g_Wq16[i]  = __float2half_rn(wq[i]);
    if (i < KVDIM * CDIM) g_Wkv16[i] = __float2half_rn(wkv[i]);
}

// ---------------- convert fp32 activations to fp16 ------------------------
__global__ __launch_bounds__(256) void convert_x(
    const float* __restrict__ xq, const float* __restrict__ xkv)
{
    const size_t i = (size_t)blockIdx.x * 256 + threadIdx.x;      // float4 index
    float4 v = ((const float4*)xq)[i];
    __half2 a = __floats2half2_rn(v.x, v.y);
    __half2 b = __floats2half2_rn(v.z, v.w);
    ((uint2*)g_Xq16)[i] = make_uint2(*(uint32_t*)&a, *(uint32_t*)&b);
    v = ((const float4*)xkv)[i];
    a = __floats2half2_rn(v.x, v.y);
    b = __floats2half2_rn(v.z, v.w);
    ((uint2*)g_Xkv16)[i] = make_uint2(*(uint32_t*)&a, *(uint32_t*)&b);
}

// ---------------- depthwise 3x3, pad 1 — row-strip smem version -----------
__global__ __launch_bounds__(160) void dwconv3x3_v2(
    const float* __restrict__ X, const float* __restrict__ Wd,
    float* __restrict__ Y, int C)
{
    __shared__ float s[10][WIDTH];
    const int b = blockIdx.z, ch = blockIdx.y;
    const int r0 = blockIdx.x * 8;
    const int w = threadIdx.x;
    const float* xp = X + ((size_t)b * C + ch) * HW;
    #pragma unroll
    for (int i = 0; i < 10; i++) {
        int r = r0 - 1 + i;
        s[i][w] = (r >= 0 && r < WIDTH) ? xp[r * WIDTH + w] : 0.f;
    }
    const float* wp = Wd + ch * 9;
    float c00 = wp[0], c01 = wp[1], c02 = wp[2];
    float c10 = wp[3], c11 = wp[4], c12 = wp[5];
    float c20 = wp[6], c21 = wp[7], c22 = wp[8];
    __syncthreads();
    const bool wl = (w > 0), wr = (w < WIDTH - 1);
    float* yp = Y + ((size_t)b * C + ch) * HW + r0 * WIDTH + w;
    #pragma unroll
    for (int r = 0; r < 8; r++) {
        float a0 = wl ? s[r][w-1] : 0.f, a1 = s[r][w],   a2 = wr ? s[r][w+1] : 0.f;
        float b0 = wl ? s[r+1][w-1] : 0.f, b1 = s[r+1][w], b2 = wr ? s[r+1][w+1] : 0.f;
        float d0 = wl ? s[r+2][w-1] : 0.f, d1 = s[r+2][w], d2 = wr ? s[r+2][w+1] : 0.f;
        yp[r * WIDTH] = c00*a0 + c01*a1 + c02*a2
                      + c10*b0 + c11*b1 + c12*b2
                      + c20*d0 + c21*d1 + c22*d2;
    }
}

// ---- depthwise 3x3 for v: fp32 in (KVDIM stride) -> fp16 out -------------
__global__ __launch_bounds__(160) void dwconv3x3_vh(
    const float* __restrict__ X, const float* __restrict__ Wd,
    __half* __restrict__ Yh)
{
    __shared__ float s[10][WIDTH];
    const int b = blockIdx.z, ch = blockIdx.y;
    const int r0 = blockIdx.x * 8;
    const int w = threadIdx.x;
    const float* xp = X + ((size_t)b * KVDIM + ch) * HW;    // X pre-offset to v half
    #pragma unroll
    for (int i = 0; i < 10; i++) {
        int r = r0 - 1 + i;
        s[i][w] = (r >= 0 && r < WIDTH) ? xp[r * WIDTH + w] : 0.f;
    }
    const float* wp = Wd + ch * 9;
    float c00 = wp[0], c01 = wp[1], c02 = wp[2];
    float c10 = wp[3], c11 = wp[4], c12 = wp[5];
    float c20 = wp[6], c21 = wp[7], c22 = wp[8];
    __syncthreads();
    const bool wl = (w > 0), wr = (w < WIDTH - 1);
    size_t base = ((size_t)b * CDIM + ch) * HW + r0 * WIDTH + w;
    #pragma unroll
    for (int r = 0; r < 8; r++) {
        float a0 = wl ? s[r][w-1] : 0.f, a1 = s[r][w],   a2 = wr ? s[r][w+1] : 0.f;
        float b0 = wl ? s[r+1][w-1] : 0.f, b1 = s[r+1][w], b2 = wr ? s[r+1][w+1] : 0.f;
        float d0 = wl ? s[r+2][w-1] : 0.f, d1 = s[r+2][w], d2 = wr ? s[r+2][w+1] : 0.f;
        float acc = c00*a0 + c01*a1 + c02*a2
                  + c10*b0 + c11*b1 + c12*b2
                  + c20*d0 + c21*d1 + c22*d2;
        Yh[base + r * WIDTH] = __float2half_rn(acc);
    }
}

// ---------------- zero the gram accumulators -------------------------------
__global__ void zero_acc() {
    int i = blockIdx.x * 256 + threadIdx.x;
    const int nS = BATCH * HEADS * CPH * CPH;
    const int nN = BATCH * HEADS * CPH;
    if (i < nS) g_S[i] = 0.f;
    if (i < nN) { g_NQ[i] = 0.f; g_NK[i] = 0.f; }
}

// ---------------- Gram: S[b,h,c,d] = sum_n q[c,n] k[d,n]; plus sum q^2, k^2
__global__ __launch_bounds__(256) void gram(
    const float* __restrict__ Q, const float* __restrict__ K)
{
    __shared__ float qs[32][33];
    __shared__ float ks[32][33];
    const int b = blockIdx.z, hh = blockIdx.y, split = blockIdx.x;
    const int tid = threadIdx.x;
    const float* qb = Q + ((size_t)b * CDIM  + hh * CPH) * HW;
    const float* kb = K + ((size_t)b * KVDIM + hh * CPH) * HW;
    const int chunk = HW / NSPLIT;
    const int nbeg = split * chunk;
    const int ty = tid >> 4, tx = tid & 15;
    const int lc = tid >> 3;
    const int lj = (tid & 7) * 4;

    float acc00 = 0, acc01 = 0, acc10 = 0, acc11 = 0;
    float aq0 = 0, aq1 = 0, ak0 = 0, ak1 = 0;

    for (int n0 = nbeg; n0 < nbeg + chunk; n0 += 32) {
        float4 vq = *(const float4*)&qb[(size_t)lc * HW + n0 + lj];
        float4 vk = *(const float4*)&kb[(size_t)lc * HW + n0 + lj];
        qs[lc][lj] = vq.x; qs[lc][lj+1] = vq.y; qs[lc][lj+2] = vq.z; qs[lc][lj+3] = vq.w;
        ks[lc][lj] = vk.x; ks[lc][lj+1] = vk.y; ks[lc][lj+2] = vk.z; ks[lc][lj+3] = vk.w;
        __syncthreads();
        #pragma unroll
        for (int t = 0; t < 32; t++) {
            float q0 = qs[ty*2][t],  q1 = qs[ty*2+1][t];
            float k0 = ks[tx*2][t],  k1 = ks[tx*2+1][t];
            acc00 += q0*k0; acc01 += q0*k1; acc10 += q1*k0; acc11 += q1*k1;
            if (tx == 0) { aq0 += q0*q0; aq1 += q1*q1; }
            if (ty == 0) { ak0 += k0*k0; ak1 += k1*k1; }
        }
        __syncthreads();
    }
    float* Sb = g_S + (size_t)(b * HEADS + hh) * CPH * CPH;
    atomicAdd(&Sb[(ty*2    ) * CPH + tx*2    ], acc00);
    atomicAdd(&Sb[(ty*2    ) * CPH + tx*2 + 1], acc01);
    atomicAdd(&Sb[(ty*2 + 1) * CPH + tx*2    ], acc10);
    atomicAdd(&Sb[(ty*2 + 1) * CPH + tx*2 + 1], acc11);
    if (tx == 0) {
        atomicAdd(&g_NQ[(b * HEADS + hh) * CPH + ty*2    ], aq0);
        atomicAdd(&g_NQ[(b * HEADS + hh) * CPH + ty*2 + 1], aq1);
    }
    if (ty == 0) {
        atomicAdd(&g_NK[(b * HEADS + hh) * CPH + tx*2    ], ak0);
        atomicAdd(&g_NK[(b * HEADS + hh) * CPH + tx*2 + 1], ak1);
    }
}

// ---------------- softmax over d with L2-norm scaling + temperature --------
__global__ void softmax_attn(const float* __restrict__ temp) {
    const int bh = blockIdx.x;
    const int h  = bh % HEADS;
    const int d  = threadIdx.x;
    const float t = temp[h];
    float nk = fmaxf(sqrtf(g_NK[bh * CPH + d]), 1e-12f);
    for (int c = 0; c < CPH; c++) {
        float nq = fmaxf(sqrtf(g_NQ[bh * CPH + c]), 1e-12f);
        float v = g_S[bh * CPH * CPH + c * CPH + d] / (nq * nk) * t;
        float m = v;
        #pragma unroll
        for (int o = 16; o; o >>= 1) m = fmaxf(m, __shfl_xor_sync(~0u, m, o));
        float e = __expf(v - m);
        float s = e;
        #pragma unroll
        for (int o = 16; o; o >>= 1) s += __shfl_xor_sync(~0u, s, o);
        g_A[bh * CPH * CPH + c * CPH + d] = e / s;
    }
}

// ---------------- fold: M[b,o,g] = sum_c Wout[o, h*32+c] * A[b,h,c,d] ------
__global__ __launch_bounds__(256) void foldM(const float* __restrict__ Wout) {
    const int b = blockIdx.y;
    const int idx = blockIdx.x * 256 + threadIdx.x;
    const int o = idx / CDIM, g = idx % CDIM;
    const int h = g / CPH, d = g % CPH;
    const float* Ab = g_A + (size_t)(b * HEADS + h) * CPH * CPH;
    float acc = 0.f;
    #pragma unroll
    for (int c = 0; c < CPH; c++)
        acc += Wout[o * CDIM + h * CPH + c] * Ab[c * CPH + d];
    g_M16[(size_t)b * CDIM * CDIM + idx] = __float2half_rn(acc);
}

// ---------------- launch --------------------------------------------------
extern "C" void kernel_launch(void* const* d_in, const int* in_sizes, int n_in,
                              void* d_out, int out_size)
{
    const float* x_q   = (const float*)d_in[0];
    const float* x_kv  = (const float*)d_in[1];
    const float* w_q   = (const float*)d_in[2];
    const float* w_kv  = (const float*)d_in[3];
    const float* w_qdw = (const float*)d_in[4];
    const float* w_kvdw= (const float*)d_in[5];
    const float* w_out = (const float*)d_in[6];
    const float* temp  = (const float*)d_in[7];
    float* out = (float*)d_out;

    float *bq, *bkv, *bqd, *bkvd;
    __half *wq16, *wkv16, *m16, *xq16, *xkv16, *v16;
    cudaGetSymbolAddress((void**)&bq,    g_q);
    cudaGetSymbolAddress((void**)&bkv,   g_kv);
    cudaGetSymbolAddress((void**)&bqd,   g_qd);
    cudaGetSymbolAddress((void**)&bkvd,  g_kvd);
    cudaGetSymbolAddress((void**)&wq16,  g_Wq16);
    cudaGetSymbolAddress((void**)&wkv16, g_Wkv16);
    cudaGetSymbolAddress((void**)&m16,   g_M16);
    cudaGetSymbolAddress((void**)&xq16,  g_Xq16);
    cudaGetSymbolAddress((void**)&xkv16, g_Xkv16);
    cudaGetSymbolAddress((void**)&v16,   g_V16);

    cudaFuncSetAttribute(gemm_fp16, cudaFuncAttributeMaxDynamicSharedMemorySize, SM_TOTAL);

    // 0) convert weights + activations to fp16
    convert_w<<<(KVDIM * CDIM + 255) / 256, 256>>>(w_q, w_kv);
    convert_x<<<(int)(((size_t)BATCH * CDIM * HW / 4) / 256), 256>>>(x_q, x_kv);
    // 1) q = W_q @ x_q
    gemm_fp16<<<dim3(HW/128, CDIM/64, BATCH), 256, SM_TOTAL>>>(
        wq16, xq16, bq, CDIM, 0, (long)CDIM * HW);
    // 2) kv = W_kv @ x_kv (384 outputs)
    gemm_fp16<<<dim3(HW/128, KVDIM/64, BATCH), 256, SM_TOTAL>>>(
        wkv16, xkv16, bkv, KVDIM, 0, (long)CDIM * HW);
    // 3) depthwise 3x3: q (fp32), k (fp32, first half of kv), v (fp16 out)
    dwconv3x3_v2<<<dim3(WIDTH/8, CDIM, BATCH), WIDTH>>>(bq, w_qdw, bqd, CDIM);
    dwconv3x3_v2<<<dim3(WIDTH/8, CDIM, BATCH), WIDTH>>>(bkv, w_kvdw, bkvd, KVDIM);
    dwconv3x3_vh<<<dim3(WIDTH/8, CDIM, BATCH), WIDTH>>>(
        bkv + (size_t)CDIM * HW, w_kvdw + CDIM * 9, v16);
    // 4) zero gram accumulators
    zero_acc<<<(BATCH*HEADS*CPH*CPH + 255)/256, 256>>>();
    // 5) gram + norms (k = first KVDIM-strided half of kvd)
    gram<<<dim3(NSPLIT, HEADS, BATCH), 256>>>(bqd, bkvd);
    // 6) softmax with normalization + temperature
    softmax_attn<<<BATCH * HEADS, 32>>>(temp);
    // 7) fold W_out with attention -> fp16 M
    foldM<<<dim3(CDIM*CDIM/256, BATCH), 256>>>(w_out);
    // 8) out = M_b @ v
    gemm_fp16<<<dim3(HW/128, CDIM/64, BATCH), 256, SM_TOTAL>>>(
        m16, v16, out, CDIM, (long)CDIM * CDIM, (long)CDIM * HW);
}